// round 3
// baseline (speedup 1.0000x reference)
#include <cuda_runtime.h>
#include <cstdint>

#define NB      8192
#define MDIM    32
#define NDIM    16
#define MAXIT   100
#define TOLF    1e-2f
#define ALPHAF  0.5f

typedef unsigned long long u64;

// ---- static device scratch (no dynamic allocation anywhere) ----
__device__ float    g_P    [NB * MDIM * MDIM];               // 32 MB : P = I - A K A^T
__device__ float    g_H1   [NB * NDIM * MDIM];               // 16 MB : H1 = T1 A^T
__device__ float2   g_zhist[(size_t)NB * MAXIT * 32];        // ~210 MB
__device__ unsigned g_flagbits[4];
__device__ int      g_J;

// ---- packed fp32x2 helpers ----
__device__ __forceinline__ u64 fma2(u64 a, u64 b, u64 c) {
    u64 d; asm("fma.rn.f32x2 %0,%1,%2,%3;" : "=l"(d) : "l"(a), "l"(b), "l"(c)); return d;
}
__device__ __forceinline__ u64 add2(u64 a, u64 b) {
    u64 d; asm("add.rn.f32x2 %0,%1,%2;" : "=l"(d) : "l"(a), "l"(b)); return d;
}
__device__ __forceinline__ float red2(u64 a) {
    float lo, hi; asm("mov.b64 {%0,%1},%2;" : "=f"(lo), "=f"(hi) : "l"(a)); return lo + hi;
}

__device__ __forceinline__ float dot16p(const u64* a, const u64* v) {
    u64 c0 = fma2(a[0], v[0], 0ull);
    u64 c1 = fma2(a[1], v[1], 0ull);
    u64 c2 = fma2(a[2], v[2], 0ull);
    u64 c3 = fma2(a[3], v[3], 0ull);
    c0 = fma2(a[4], v[4], c0);
    c1 = fma2(a[5], v[5], c1);
    c2 = fma2(a[6], v[6], c2);
    c3 = fma2(a[7], v[7], c3);
    return red2(add2(add2(c0, c1), add2(c2, c3)));
}
__device__ __forceinline__ float dot32p(const u64* a, const u64* v) {
    u64 c0 = fma2(a[0], v[0], 0ull);
    u64 c1 = fma2(a[1], v[1], 0ull);
    u64 c2 = fma2(a[2], v[2], 0ull);
    u64 c3 = fma2(a[3], v[3], 0ull);
#pragma unroll
    for (int j = 1; j < 4; j++) {
        c0 = fma2(a[4 * j + 0], v[4 * j + 0], c0);
        c1 = fma2(a[4 * j + 1], v[4 * j + 1], c1);
        c2 = fma2(a[4 * j + 2], v[4 * j + 2], c2);
        c3 = fma2(a[4 * j + 3], v[4 * j + 3], c3);
    }
    return red2(add2(add2(c0, c1), add2(c2, c3)));
}

// -------------------------------------------------------------------------
__global__ void init_flags_kernel() {
    int t = threadIdx.x;
    if (t < 4) g_flagbits[t] = 0u;
}

// -------------------------------------------------------------------------
// Per-batch precompute:
//   K  = (0.5 I + A^T A)^{-1}            (16x16, via Gauss-Jordan; SPD, diag>=0.5)
//   T1 = I - (A^T A) K                   (16x16)
//   G  = K A^T                           (16x32)
//   P  = I - A G                         (32x32)  -> g_P   (row-major)
//   H1 = T1 A^T                          (16x32)  -> g_H1  (row-major)
__global__ void __launch_bounds__(128) precompute_kernel(const float* __restrict__ A_g) {
    __shared__ __align__(16) float A_sh [4][MDIM * NDIM];
    __shared__ __align__(16) float F_sh [4][NDIM * NDIM];
    __shared__ float aug_sh[4][NDIM * 33];
    __shared__ float f_sh  [4][NDIM];
    __shared__ __align__(16) float K_sh [4][NDIM * NDIM];
    __shared__ __align__(16) float T1_sh[4][NDIM * NDIM];
    __shared__ __align__(16) float G_sh [4][NDIM * MDIM];

    const int lane  = threadIdx.x & 31;
    const int w     = threadIdx.x >> 5;
    const int batch = blockIdx.x * 4 + w;

    // load A (row-major 32x16)
    const float4* Ab4 = reinterpret_cast<const float4*>(A_g + (size_t)batch * MDIM * NDIM);
    float4* As4 = reinterpret_cast<float4*>(A_sh[w]);
#pragma unroll
    for (int j = 0; j < 4; j++) As4[lane * 4 + j] = Ab4[lane * 4 + j];
    __syncwarp();

    // F = A^T A  (lanes 0..15 compute row lane)
    if (lane < NDIM) {
        float acc[16];
#pragma unroll
        for (int j = 0; j < 16; j++) acc[j] = 0.f;
#pragma unroll 4
        for (int k = 0; k < MDIM; k++) {
            float aki = A_sh[w][k * NDIM + lane];
            const float4* row = reinterpret_cast<const float4*>(&A_sh[w][k * NDIM]);
            float4 r0 = row[0], r1 = row[1], r2 = row[2], r3 = row[3];
            acc[0]  += aki * r0.x;  acc[1]  += aki * r0.y;
            acc[2]  += aki * r0.z;  acc[3]  += aki * r0.w;
            acc[4]  += aki * r1.x;  acc[5]  += aki * r1.y;
            acc[6]  += aki * r1.z;  acc[7]  += aki * r1.w;
            acc[8]  += aki * r2.x;  acc[9]  += aki * r2.y;
            acc[10] += aki * r2.z;  acc[11] += aki * r2.w;
            acc[12] += aki * r3.x;  acc[13] += aki * r3.y;
            acc[14] += aki * r3.z;  acc[15] += aki * r3.w;
        }
#pragma unroll
        for (int j = 0; j < 16; j++) F_sh[w][lane * 16 + j] = acc[j];
    }
    __syncwarp();

    // augmented [F + 0.5 I | I]
#pragma unroll
    for (int r = 0; r < NDIM; r++) {
        float v;
        if (lane < 16) v = F_sh[w][r * 16 + lane] + ((r == lane) ? 0.5f : 0.f);
        else           v = ((lane - 16) == r) ? 1.f : 0.f;
        aug_sh[w][r * 33 + lane] = v;
    }
    __syncwarp();

    // Gauss-Jordan (no pivoting; SPD)
#pragma unroll 1
    for (int p = 0; p < NDIM; p++) {
        float piv = 1.0f / aug_sh[w][p * 33 + p];
        if (lane < NDIM) f_sh[w][lane] = aug_sh[w][lane * 33 + p];
        __syncwarp();
        float prow = aug_sh[w][p * 33 + lane] * piv;
        aug_sh[w][p * 33 + lane] = prow;
#pragma unroll
        for (int r = 0; r < NDIM; r++) {
            if (r != p) aug_sh[w][r * 33 + lane] -= f_sh[w][r] * prow;
        }
        __syncwarp();
    }

    // K_sh from aug right half
#pragma unroll
    for (int e = 0; e < 8; e++) {
        int idx = e * 32 + lane;
        int i = idx >> 4, j = idx & 15;
        K_sh[w][idx] = aug_sh[w][i * 33 + 16 + j];
    }
    __syncwarp();

    // T1 = I - F K
#pragma unroll
    for (int e = 0; e < 8; e++) {
        int idx = e * 32 + lane;
        int i = idx >> 4, j = idx & 15;
        float s = (i == j) ? 1.f : 0.f;
#pragma unroll
        for (int m = 0; m < 16; m++)
            s -= F_sh[w][i * 16 + m] * K_sh[w][m * 16 + j];
        T1_sh[w][idx] = s;
    }
    __syncwarp();

    // preload this lane's A row into registers (avoids strided LDS conflicts)
    float a_reg[16];
    {
        const float4* row = reinterpret_cast<const float4*>(&A_sh[w][lane * NDIM]);
#pragma unroll
        for (int j = 0; j < 4; j++) {
            float4 v = row[j];
            a_reg[4 * j] = v.x; a_reg[4 * j + 1] = v.y; a_reg[4 * j + 2] = v.z; a_reg[4 * j + 3] = v.w;
        }
    }

    // G[i][lane] = K row i . A row lane   (column `lane` of G across i)
#pragma unroll
    for (int i = 0; i < NDIM; i++) {
        float s = 0.f;
#pragma unroll
        for (int m = 0; m < 16; m++) s += K_sh[w][i * 16 + m] * a_reg[m];
        G_sh[w][i * MDIM + lane] = s;
    }
    // H1[i][lane] = T1 row i . A row lane
    float* H1b = g_H1 + (size_t)batch * NDIM * MDIM;
#pragma unroll
    for (int i = 0; i < NDIM; i++) {
        float s = 0.f;
#pragma unroll
        for (int m = 0; m < 16; m++) s += T1_sh[w][i * 16 + m] * a_reg[m];
        H1b[i * MDIM + lane] = s;
    }
    __syncwarp();

    // P[e][lane] = delta(e,lane) - A row e . G col lane
    float* Pb = g_P + (size_t)batch * MDIM * MDIM;
#pragma unroll
    for (int e = 0; e < MDIM; e++) {
        float s = (e == lane) ? 1.f : 0.f;
#pragma unroll
        for (int m = 0; m < 16; m++)
            s -= A_sh[w][e * NDIM + m] * G_sh[w][m * MDIM + lane];
        Pb[e * MDIM + lane] = s;
    }
}

// -------------------------------------------------------------------------
// One warp per batch, 2-stage iteration:
//   q = pdiff - (z1-z2) + u                 (16)
//   r = 2x3 - z3 - b + A q                  (32)
//   w = P r ; t = H1 r                      (parallel)
//   z1' = x1 - a*grad - t ; z2' = x2 + a*grad + t ; z3' = x3 - w
// Convergence flags accumulate in a per-warp register bitmask (no in-loop STG).
__global__ void __launch_bounds__(128, 4) iterate_kernel(
        const float* __restrict__ u_g,
        const float* __restrict__ A_g,
        const float* __restrict__ b_g) {
    __shared__ __align__(16) float q_sh [4][16];
    __shared__ __align__(16) float r_sh [4][32];
    __shared__ unsigned sbits[4];

    const int lane  = threadIdx.x & 31;
    const int w     = threadIdx.x >> 5;
    const int batch = blockIdx.x * 4 + w;
    const int i16   = lane & 15;
    const int half  = lane >> 4;
    const float sgn = half ? -1.f : 1.f;
    const int kbase = half * 16;

    if (threadIdx.x < 4) sbits[threadIdx.x] = 0u;

    const float* Ab = A_g + (size_t)batch * 512;

    // A row `lane` (8 packed f32x2)
    u64 ar[8];
    {
        const ulonglong2* Ab2 = reinterpret_cast<const ulonglong2*>(Ab);
#pragma unroll
        for (int j = 0; j < 4; j++) {
            ulonglong2 v = Ab2[lane * 4 + j];
            ar[2 * j] = v.x; ar[2 * j + 1] = v.y;
        }
    }
    // P row `lane` (16 packed)
    u64 pr[16];
    {
        const ulonglong2* Pb2 = reinterpret_cast<const ulonglong2*>(
            g_P + (size_t)batch * MDIM * MDIM + lane * MDIM);
#pragma unroll
        for (int j = 0; j < 8; j++) {
            ulonglong2 v = Pb2[j];
            pr[2 * j] = v.x; pr[2 * j + 1] = v.y;
        }
    }
    // H1 row i16, half-columns [kbase, kbase+16) (8 packed)
    u64 h1[8];
    {
        const ulonglong2* Hb2 = reinterpret_cast<const ulonglong2*>(
            g_H1 + (size_t)batch * NDIM * MDIM + i16 * MDIM + kbase);
#pragma unroll
        for (int j = 0; j < 4; j++) {
            ulonglong2 v = Hb2[j];
            h1[2 * j] = v.x; h1[2 * j + 1] = v.y;
        }
    }

    const float u_lo = u_g[batch * 16 + i16];
    const float bl   = b_g[batch * 32 + lane];

    float2* hist = g_zhist + (size_t)batch * 32 + lane;

    float z_a = 0.f, z_b = 0.f;
    unsigned bits = 0u;

    __syncthreads();

#pragma unroll 1
    for (int k = 1; k <= MAXIT; k++) {
        float x_a = fmaxf(z_a, 0.f);
        float x_b = fmaxf(z_b, 0.f);
        float xa_o = __shfl_xor_sync(0xffffffffu, x_a, 16);
        float za_o = __shfl_xor_sync(0xffffffffu, z_a, 16);
        float pdiff = x_a - xa_o;

        if (lane < 16) q_sh[w][lane] = pdiff - (z_a - za_o) + u_lo;
        __syncwarp();

        // stage 1: r_l = 2x3 - z3 - b + (A q)_l
        u64 qp[8];
        {
            const ulonglong2* qv = reinterpret_cast<const ulonglong2*>(&q_sh[w][0]);
#pragma unroll
            for (int j = 0; j < 4; j++) { ulonglong2 v = qv[j]; qp[2*j] = v.x; qp[2*j+1] = v.y; }
        }
        float r = 2.f * x_b - z_b - bl + dot16p(ar, qp);
        r_sh[w][lane] = r;
        __syncwarp();

        // stage 2: w = P r  and  t = H1 r  (in parallel)
        u64 rp[16];
        {
            const ulonglong2* rv = reinterpret_cast<const ulonglong2*>(&r_sh[w][0]);
#pragma unroll
            for (int j = 0; j < 8; j++) { ulonglong2 v = rv[j]; rp[2*j] = v.x; rp[2*j+1] = v.y; }
        }
        float wv = dot32p(pr, rp);
        float tp = dot16p(h1, rp + 8 * half);
        float tval = tp + __shfl_xor_sync(0xffffffffu, tp, 16);

        float grad_a = pdiff - sgn * u_lo;
        float zan = x_a - ALPHAF * grad_a - sgn * tval;
        float zbn = x_b - wv;

        float res = fmaxf(fabsf(zan - z_a), fabsf(zbn - z_b));
        unsigned bal = __ballot_sync(0xffffffffu, res >= TOLF);
        if (k < MAXIT) bits |= (unsigned)(bal != 0u) << ((k - 1) & 31);
        if ((k & 31) == 0) {
            if (lane == 0) atomicOr(&sbits[(k >> 5) - 1], bits);
            bits = 0u;
        }

        hist[(size_t)(k - 1) * NB * 32] = make_float2(zan, zbn);

        z_a = zan; z_b = zbn;
    }

    if (lane == 0) atomicOr(&sbits[3], bits);
    __syncthreads();
    if (threadIdx.x < 4) atomicOr(&g_flagbits[threadIdx.x], sbits[threadIdx.x]);
}

// -------------------------------------------------------------------------
// J = first k in [1,99] with flag 0, else 99. Bit (k-1) of word (k-1)>>5.
__global__ void select_kernel() {
    __shared__ int s;
    if (threadIdx.x == 0) s = MAXIT - 1;
    __syncthreads();
    int t = threadIdx.x;
    if (t < 4) {
        unsigned wd = g_flagbits[t];
        if (t == 3) wd |= 0xFFFFFFF8u;     // only k=97..99 valid in word 3
        unsigned inv = ~wd;
        if (inv) {
            int b = __ffs(inv) - 1;
            int k = 32 * t + b + 1;
            if (k <= MAXIT - 1) atomicMin(&s, k);
        }
    }
    __syncthreads();
    if (threadIdx.x == 0) g_J = s;
}

// z_star = history slot J. out = [u_star (8192x16), z_star (8192x64)].
__global__ void output_kernel(float* __restrict__ out) {
    int J = g_J;
    int idx = blockIdx.x * blockDim.x + threadIdx.x;
    if (idx >= NB * 64) return;
    int b = idx >> 6;
    int j = idx & 63;
    size_t base = ((size_t)J * NB + b) * 32;
    float2 vlo = g_zhist[base + (j & 31)];
    float z = (j < 32) ? vlo.x : vlo.y;
    out[NB * 16 + idx] = z;
    if (j < 16) {
        float2 vhi = g_zhist[base + 16 + j];
        out[b * 16 + j] = vlo.x - vhi.x;   // u = z1 - z2
    }
}

// -------------------------------------------------------------------------
extern "C" void kernel_launch(void* const* d_in, const int* in_sizes, int n_in,
                              void* d_out, int out_size) {
    const float* u_nom = (const float*)d_in[0];
    const float* A     = (const float*)d_in[1];
    const float* b     = (const float*)d_in[2];
    float* out = (float*)d_out;

    init_flags_kernel<<<1, 32>>>();
    precompute_kernel<<<NB / 4, 128>>>(A);
    iterate_kernel<<<NB / 4, 128>>>(u_nom, A, b);
    select_kernel<<<1, 128>>>();
    output_kernel<<<(NB * 64 + 255) / 256, 256>>>(out);
}